// round 5
// baseline (speedup 1.0000x reference)
#include <cuda_runtime.h>
#include <cuda_bf16.h>
#include <cstddef>

// ---------------- problem constants ----------------
#define B_      64
#define T_      512
#define NINP    64
#define NHID    1024
#define THARM   256
#define TSPIKE  256
#define DT_F    0.042f
#define THRESH  0.008f
#define RESET_F 0.001f
// R_MEM * C_MEM = 5.0 * 0.005
#define RC_F    (5.0f * 0.005f)

#define KS      8          // split-K factor for the recurrent GEMM
#define KC      (NHID/KS)  // 128

// ---------------- device scratch (no cudaMalloc allowed) ----------------
__device__ float g_xw[THARM * B_ * NHID];   // 256*64*1024 floats = 64 Mi floats (67 MB): x_t @ x2h
__device__ float g_part[KS * B_ * NHID];    // split-K partials (2 MB)
__device__ float g_hy[B_ * NHID];
__device__ float g_hz[B_ * NHID];
__device__ float g_hyW[B_ * NHID];

// ---------------- init: zero states ----------------
__global__ void init_kernel() {
    int tid = blockIdx.x * blockDim.x + threadIdx.x;   // 65536 threads
    g_hy[tid] = 0.0f;
    g_hz[tid] = 0.0f;
}

// ---------------- K0: g_xw[t][b][h] = x[b,t,:] @ x2h[:,h]  (t < 256) ----------------
// Treated as GEMM with rows r = t*64 + b (16384 rows), K=64, N=1024.
// Block tile [64 rows x 64 cols], 256 threads, 4x4 microtile.
__global__ void xw_kernel(const float* __restrict__ x, const float* __restrict__ x2h) {
    __shared__ float xs[64][64];   // [row][k]
    __shared__ float ws[64][64];   // [k][c]
    int tid = threadIdx.x;
    int r0 = blockIdx.x * 64;
    int h0 = blockIdx.y * 64;

    // load x tile (rows r0..r0+63, k 0..63), float4 granularity
    for (int i = tid; i < 64 * 16; i += 256) {
        int row = i >> 4, q = i & 15;
        int r = r0 + row;
        int b = r & 63;
        int t = r >> 6;
        ((float4*)xs[row])[q] =
            ((const float4*)(x + (size_t)b * (T_ * NINP) + (size_t)t * NINP))[q];
    }
    // load x2h tile (k 0..63, cols h0..h0+63)
    for (int i = tid; i < 64 * 16; i += 256) {
        int k = i >> 4, q = i & 15;
        ((float4*)ws[k])[q] = ((const float4*)(x2h + (size_t)k * NHID + h0))[q];
    }
    __syncthreads();

    int tx = tid & 15, ty = tid >> 4;   // 16x16 threads
    float acc[4][4] = {};
#pragma unroll 16
    for (int k = 0; k < 64; k++) {
        float4 bv = ((float4*)ws[k])[tx];
        float a0 = xs[ty * 4 + 0][k];
        float a1 = xs[ty * 4 + 1][k];
        float a2 = xs[ty * 4 + 2][k];
        float a3 = xs[ty * 4 + 3][k];
        acc[0][0] = fmaf(a0, bv.x, acc[0][0]); acc[0][1] = fmaf(a0, bv.y, acc[0][1]);
        acc[0][2] = fmaf(a0, bv.z, acc[0][2]); acc[0][3] = fmaf(a0, bv.w, acc[0][3]);
        acc[1][0] = fmaf(a1, bv.x, acc[1][0]); acc[1][1] = fmaf(a1, bv.y, acc[1][1]);
        acc[1][2] = fmaf(a1, bv.z, acc[1][2]); acc[1][3] = fmaf(a1, bv.w, acc[1][3]);
        acc[2][0] = fmaf(a2, bv.x, acc[2][0]); acc[2][1] = fmaf(a2, bv.y, acc[2][1]);
        acc[2][2] = fmaf(a2, bv.z, acc[2][2]); acc[2][3] = fmaf(a2, bv.w, acc[2][3]);
        acc[3][0] = fmaf(a3, bv.x, acc[3][0]); acc[3][1] = fmaf(a3, bv.y, acc[3][1]);
        acc[3][2] = fmaf(a3, bv.z, acc[3][2]); acc[3][3] = fmaf(a3, bv.w, acc[3][3]);
    }
#pragma unroll
    for (int i = 0; i < 4; i++) {
        float4 v = make_float4(acc[i][0], acc[i][1], acc[i][2], acc[i][3]);
        ((float4*)(g_xw + (size_t)(r0 + ty * 4 + i) * NHID + h0))[tx] = v;
    }
}

// ---------------- per-step recurrent GEMM: g_part[ks] += g_hy @ h2h (split-K) ----------------
// grid = 256 blocks: (coltile 0..31) x (ks 0..7). Block tile [64 x 32], K-chunk 128.
// 8 warps: warp w -> rows [8w, 8w+8), lanes -> 32 cols. hy read via LDS.128 broadcast.
__global__ void __launch_bounds__(256, 2) gemm_kernel(const float* __restrict__ h2h) {
    __shared__ float sa[64][KC];   // hy rows x k    : 32 KB
    __shared__ float sb[KC][32];   // k x cols       : 16 KB
    int bid = blockIdx.x;
    int ct = bid & 31;
    int ks = bid >> 5;
    int c0 = ct * 32;
    int k0 = ks * KC;
    int tid = threadIdx.x;

    // stage hy[64][k0..k0+127]
    for (int i = tid; i < 64 * (KC / 4); i += 256) {
        int row = i >> 5, q = i & 31;
        ((float4*)sa[row])[q] = ((const float4*)(g_hy + (size_t)row * NHID + k0))[q];
    }
    // stage h2h[k0..k0+127][c0..c0+31]
    for (int i = tid; i < KC * 8; i += 256) {
        int k = i >> 3, q = i & 7;
        ((float4*)sb[k])[q] = ((const float4*)(h2h + (size_t)(k0 + k) * NHID + c0))[q];
    }
    __syncthreads();

    int w = tid >> 5;
    int lane = tid & 31;
    int m0 = w * 8;
    float acc[8] = {};
#pragma unroll 8
    for (int k = 0; k < KC; k += 4) {
        float b0 = sb[k + 0][lane];
        float b1 = sb[k + 1][lane];
        float b2 = sb[k + 2][lane];
        float b3 = sb[k + 3][lane];
#pragma unroll
        for (int r = 0; r < 8; r++) {
            float4 av = *(const float4*)&sa[m0 + r][k];   // broadcast across lanes
            acc[r] = fmaf(av.x, b0, acc[r]);
            acc[r] = fmaf(av.y, b1, acc[r]);
            acc[r] = fmaf(av.z, b2, acc[r]);
            acc[r] = fmaf(av.w, b3, acc[r]);
        }
    }
    float* dst = g_part + ((size_t)ks << 16);   // ks * 64*1024
#pragma unroll
    for (int r = 0; r < 8; r++)
        dst[(size_t)(m0 + r) * NHID + c0 + lane] = acc[r];
}

// ---------------- per-step update: tanh + Euler, write state + outputs ----------------
__global__ void update_kernel(int t,
                              const float* __restrict__ bias,
                              const float* __restrict__ gamma,
                              const float* __restrict__ eps,
                              float* __restrict__ out_hys,
                              float* __restrict__ out_hzs) {
    int tid = blockIdx.x * blockDim.x + threadIdx.x;   // 0..65535
    int h = tid & (NHID - 1);
    int b = tid >> 10;

    float acc = 0.0f;
#pragma unroll
    for (int s = 0; s < KS; s++)
        acc += g_part[((size_t)s << 16) + tid];

    float xw = g_xw[((size_t)t << 16) + tid];
    float z = tanhf(xw + acc + bias[h]);

    float hy = g_hy[tid];
    float hz = g_hz[tid];
    hz = hz + DT_F * (z - gamma[h] * hy - eps[h] * hz);
    hy = hy + DT_F * hz;
    g_hy[tid] = hy;
    g_hz[tid] = hz;

    size_t o = ((size_t)b * T_ + t) * NHID + h;
    out_hys[o] = hy;
    out_hzs[o] = hz;
}

// ---------------- hyW = sum of split-K partials (after final gemm on frozen hy) ----------------
__global__ void hyw_kernel() {
    int tid = blockIdx.x * blockDim.x + threadIdx.x;   // 65536
    float acc = 0.0f;
#pragma unroll
    for (int s = 0; s < KS; s++)
        acc += g_part[((size_t)s << 16) + tid];
    g_hyW[tid] = acc;
}

// ---------------- spiking phase: per-(b,h) LIF recurrence over 256 steps ----------------
__global__ void spike_kernel(float* __restrict__ out_us, float* __restrict__ out_spk) {
    int tid = blockIdx.x * blockDim.x + threadIdx.x;   // 0..65535
    int h = tid & (NHID - 1);
    int b = tid >> 10;
    float hyw = g_hyW[tid];
    float u = 0.0f;
    size_t obase = (size_t)b * (TSPIKE * NHID) + h;
#pragma unroll 4
    for (int t = 0; t < TSPIKE; t++) {
        float spike = (u > THRESH) ? 1.0f : 0.0f;
        if (spike == 1.0f) u = RESET_F;
        float xw = g_xw[((size_t)t << 16) + tid];
        u = u + ((-u + hyw + xw) * RC_F) * DT_F;
        size_t o = obase + (size_t)t * NHID;
        out_us[o] = u;
        out_spk[o] = spike;
    }
}

// ---------------- broadcast final hy/hz into t >= 256 of hys/hzs ----------------
__global__ void bcast_kernel(float* __restrict__ out_hys, float* __restrict__ out_hzs) {
    size_t idx = (size_t)blockIdx.x * blockDim.x + threadIdx.x;  // < 64*256*1024
    int h = (int)(idx & (NHID - 1));
    size_t r = idx >> 10;
    int t = (int)(r & (TSPIKE - 1));
    int b = (int)(r >> 8);
    float hy = g_hy[(b << 10) + h];
    float hz = g_hz[(b << 10) + h];
    size_t o = ((size_t)b * T_ + THARM + t) * NHID + h;
    out_hys[o] = hy;
    out_hzs[o] = hz;
}

// ---------------- launcher ----------------
extern "C" void kernel_launch(void* const* d_in, const int* in_sizes, int n_in,
                              void* d_out, int out_size) {
    const float* x     = (const float*)d_in[0];
    const float* x2h   = (const float*)d_in[1];
    const float* h2h   = (const float*)d_in[2];
    const float* bias  = (const float*)d_in[3];
    const float* gamma = (const float*)d_in[4];
    const float* eps   = (const float*)d_in[5];

    float* out = (float*)d_out;
    // output layout: hys (B,T,H) | hzs (B,T,H) | us (B,256,H) | spikes (B,256,H)
    float* out_hys = out;
    float* out_hzs = out + (size_t)B_ * T_ * NHID;            // +33554432
    float* out_us  = out_hzs + (size_t)B_ * T_ * NHID;        // +67108864
    float* out_spk = out_us + (size_t)B_ * TSPIKE * NHID;     // +83886080

    init_kernel<<<256, 256>>>();
    xw_kernel<<<dim3(256, 16), 256>>>(x, x2h);

    for (int t = 0; t < THARM; t++) {
        gemm_kernel<<<256, 256>>>(h2h);
        update_kernel<<<256, 256>>>(t, bias, gamma, eps, out_hys, out_hzs);
    }

    // hyW = hy_final @ h2h (hy frozen during spiking phase)
    gemm_kernel<<<256, 256>>>(h2h);
    hyw_kernel<<<256, 256>>>();

    spike_kernel<<<256, 256>>>(out_us, out_spk);
    bcast_kernel<<<65536, 256>>>(out_hys, out_hzs);
}